// round 2
// baseline (speedup 1.0000x reference)
#include <cuda_runtime.h>
#include <cuda_bf16.h>
#include <math.h>

// instant-NGP HashGrid + 2-layer MLP, fused. TWO LANES PER POINT:
// lane q in {0,1} owns corner offset ox=q, so the x-adjacent corner pair
// lands in adjacent lanes of the SAME warp-wide LDG -> the coalescer merges
// them into one wavefront when they share a 128B line (always-ish for dense
// levels, ~50% for hashed levels). enc is kept packed as bf16x2 per level to
// cut registers (occupancy 32 -> 40 warps/SM).

#define NPTS (64 * 64 * 64)
#define NLEV 16
#define TSIZE (1u << 19)
#define TMASK (TSIZE - 1u)

__device__ __forceinline__ int level_res(int l) {
    const int R[NLEV] = {16, 23, 33, 48, 70, 101, 147, 212,
                         307, 445, 645, 933, 1351, 1955, 2830, 4096};
    return R[l];
}

__global__ void __launch_bounds__(256, 5)
ngp_fused_pair_kernel(const float* __restrict__ pts,
                      const float2* __restrict__ table,   // [L*T] float2
                      const float* __restrict__ w1,       // [64,32]
                      const float* __restrict__ w2,       // [64]
                      float* __restrict__ out)            // [NPTS]
{
    __shared__ float s_w1[64 * 32];
    __shared__ float s_w2[64];

    const int tid = threadIdx.x;
    for (int i = tid; i < 64 * 32; i += 256) s_w1[i] = w1[i];
    if (tid < 64) s_w2[tid] = w2[tid];
    __syncthreads();

    const int t = blockIdx.x * 256 + tid;
    const int p = t >> 1;        // point id
    const int q = t & 1;         // which x-corner this lane owns

    const float px = pts[3 * p + 0];
    const float py = pts[3 * p + 1];
    const float pz = pts[3 * p + 2];

    __nv_bfloat162 enc2[NLEV];   // packed (e0,e1) per level

#pragma unroll
    for (int l = 0; l < NLEV; ++l) {
        const int resi = level_res(l);
        const bool dense = (l < 5);
        const float res = (float)resi;

        const float x = px * res, y = py * res, z = pz * res;
        const float fx0 = floorf(x), fy0 = floorf(y), fz0 = floorf(z);
        const float fx = x - fx0, fy = y - fy0, fz = z - fz0;
        const unsigned cx = (unsigned)fx0;
        const unsigned cy = (unsigned)fy0;
        const unsigned cz = (unsigned)fz0;

        const float2* __restrict__ tab = table + (size_t)l * TSIZE;

        const unsigned ux = cx + (unsigned)q;         // this lane's x corner
        const float wxq = q ? fx : (1.0f - fx);
        const float wy[2] = {1.0f - fy, fy};
        const float wz[2] = {1.0f - fz, fz};

        unsigned iy[2], iz[2];
        if (dense) {
            const unsigned r1 = (unsigned)(resi + 1);
            iy[0] = r1 * cy;       iy[1] = r1 * (cy + 1u);
            iz[0] = r1 * r1 * cz;  iz[1] = r1 * r1 * (cz + 1u);
        } else {
            iy[0] = cy * 2654435761u;        iy[1] = (cy + 1u) * 2654435761u;
            iz[0] = cz * 805459861u;         iz[1] = (cz + 1u) * 805459861u;
        }

        float e0 = 0.0f, e1 = 0.0f;
#pragma unroll
        for (int c = 0; c < 4; ++c) {
            const int oy = (c >> 1) & 1, oz = c & 1;
            unsigned idx;
            if (dense) idx = (ux + iy[oy] + iz[oz]) & TMASK;
            else       idx = (ux ^ iy[oy] ^ iz[oz]) & TMASK;
            const float2 f = __ldg(tab + idx);
            const float w = wxq * wy[oy] * wz[oz];
            e0 = fmaf(w, f.x, e0);
            e1 = fmaf(w, f.y, e1);
        }
        // combine the two x-corner halves across the lane pair (fp32, then
        // single bf16 rounding)
        e0 += __shfl_xor_sync(0xffffffffu, e0, 1);
        e1 += __shfl_xor_sync(0xffffffffu, e1, 1);
        enc2[l] = __floats2bfloat162_rn(e0, e1);
    }

    // unpack once to fp32 for the MLP (gather temporaries are dead here)
    float enc[32];
#pragma unroll
    for (int l = 0; l < NLEV; ++l) {
        const float2 v = __bfloat1622float2(enc2[l]);
        enc[2 * l + 0] = v.x;
        enc[2 * l + 1] = v.y;
    }

    // MLP split across the lane pair: lane q handles rows [32q, 32q+32)
    const int jbase = q << 5;
    float acc = 0.0f;
#pragma unroll 4
    for (int j = 0; j < 32; ++j) {
        const float4* __restrict__ wr = (const float4*)(s_w1 + (jbase + j) * 32);
        float h = 0.0f;
#pragma unroll
        for (int k = 0; k < 8; ++k) {
            const float4 wv = wr[k];
            h = fmaf(wv.x, enc[4 * k + 0], h);
            h = fmaf(wv.y, enc[4 * k + 1], h);
            h = fmaf(wv.z, enc[4 * k + 2], h);
            h = fmaf(wv.w, enc[4 * k + 3], h);
        }
        acc = fmaf(s_w2[jbase + j], fmaxf(h, 0.0f), acc);
    }
    acc += __shfl_xor_sync(0xffffffffu, acc, 1);
    if (q == 0) out[p] = 1.0f / (1.0f + expf(-acc));
}

extern "C" void kernel_launch(void* const* d_in, const int* in_sizes, int n_in,
                              void* d_out, int out_size)
{
    const float*  pts   = (const float*)d_in[0];   // [NPTS, 3]
    const float2* table = (const float2*)d_in[1];  // [L, T, 2]
    const float*  w1    = (const float*)d_in[2];   // [64, 32]
    const float*  w2    = (const float*)d_in[3];   // [64]
    float* out = (float*)d_out;

    ngp_fused_pair_kernel<<<(NPTS * 2) / 256, 256>>>(pts, table, w1, w2, out);
}

// round 3
// speedup vs baseline: 1.3341x; 1.3341x over previous
#include <cuda_runtime.h>
#include <cuda_bf16.h>
#include <math.h>

// instant-NGP HashGrid + 2-layer MLP, fused. 2 lanes/point (x-corner pairing),
// bf16x2 MLP (HFMA2) with weights pre-packed on device, enc kept packed in
// bf16x2 registers end-to-end. Hashed-level gathers bypass L1 (.cg) so dense
// tables stay resident.

#define NPTS (64 * 64 * 64)
#define NLEV 16
#define TSIZE (1u << 19)
#define TMASK (TSIZE - 1u)

__device__ __nv_bfloat162 g_w1p[64 * 16];   // [j][l] packed pairs of w1[j, 2l:2l+2]

__global__ void prep_weights_kernel(const float* __restrict__ w1) {
    for (int k = threadIdx.x; k < 64 * 16; k += 256) {
        const int j = k >> 4, l = k & 15;
        g_w1p[k] = __floats2bfloat162_rn(w1[j * 32 + 2 * l], w1[j * 32 + 2 * l + 1]);
    }
}

__device__ __forceinline__ int level_res(int l) {
    const int R[NLEV] = {16, 23, 33, 48, 70, 101, 147, 212,
                         307, 445, 645, 933, 1351, 1955, 2830, 4096};
    return R[l];
}

__global__ void __launch_bounds__(256, 6)
ngp_fused_bf16_kernel(const float* __restrict__ pts,
                      const float2* __restrict__ table,   // [L*T] float2
                      const float* __restrict__ w2,       // [64]
                      float* __restrict__ out)            // [NPTS]
{
    __shared__ __nv_bfloat162 s_w1p[64 * 16];
    __shared__ float s_w2[64];

    const int tid = threadIdx.x;
    for (int i = tid; i < 64 * 16; i += 256) s_w1p[i] = g_w1p[i];
    if (tid < 64) s_w2[tid] = w2[tid];
    __syncthreads();

    const int t = blockIdx.x * 256 + tid;
    const int p = t >> 1;        // point id
    const int q = t & 1;         // which x-corner this lane owns

    const float px = pts[3 * p + 0];
    const float py = pts[3 * p + 1];
    const float pz = pts[3 * p + 2];

    __nv_bfloat162 enc2[NLEV];   // packed (e0,e1) per level — never unpacked

#pragma unroll
    for (int l = 0; l < NLEV; ++l) {
        const int resi = level_res(l);
        const bool dense = (l < 5);
        const float res = (float)resi;

        const float x = px * res, y = py * res, z = pz * res;
        const float fx0 = floorf(x), fy0 = floorf(y), fz0 = floorf(z);
        const float fx = x - fx0, fy = y - fy0, fz = z - fz0;
        const unsigned cx = (unsigned)fx0;
        const unsigned cy = (unsigned)fy0;
        const unsigned cz = (unsigned)fz0;

        const float2* __restrict__ tab = table + (size_t)l * TSIZE;

        const unsigned ux = cx + (unsigned)q;        // this lane's x corner
        const float wxq = q ? fx : (1.0f - fx);
        const float wy[2] = {1.0f - fy, fy};
        const float wz[2] = {1.0f - fz, fz};

        unsigned iy[2], iz[2];
        if (dense) {
            const unsigned r1 = (unsigned)(resi + 1);
            iy[0] = r1 * cy;       iy[1] = r1 * (cy + 1u);
            iz[0] = r1 * r1 * cz;  iz[1] = r1 * r1 * (cz + 1u);
        } else {
            iy[0] = cy * 2654435761u;        iy[1] = (cy + 1u) * 2654435761u;
            iz[0] = cz * 805459861u;         iz[1] = (cz + 1u) * 805459861u;
        }

        float e0 = 0.0f, e1 = 0.0f;
#pragma unroll
        for (int c = 0; c < 4; ++c) {
            const int oy = (c >> 1) & 1, oz = c & 1;
            float2 f;
            if (dense) {
                const unsigned idx = (ux + iy[oy] + iz[oz]) & TMASK;
                f = __ldg(tab + idx);                  // keep dense levels in L1
            } else {
                const unsigned idx = (ux ^ iy[oy] ^ iz[oz]) & TMASK;
                f = __ldcg(tab + idx);                 // bypass L1 (thrashing set)
            }
            const float w = wxq * wy[oy] * wz[oz];
            e0 = fmaf(w, f.x, e0);
            e1 = fmaf(w, f.y, e1);
        }
        // combine the two x-corner halves across the lane pair
        e0 += __shfl_xor_sync(0xffffffffu, e0, 1);
        e1 += __shfl_xor_sync(0xffffffffu, e1, 1);
        enc2[l] = __floats2bfloat162_rn(e0, e1);
    }

    // MLP in bf16x2: lane q handles rows [32q, 32q+32)
    const int jbase = q << 5;
    float acc = 0.0f;
#pragma unroll 4
    for (int j = 0; j < 32; ++j) {
        const uint4* __restrict__ wr = (const uint4*)(s_w1p + (jbase + j) * 16);
        __nv_bfloat162 h2 = __floats2bfloat162_rn(0.0f, 0.0f);
#pragma unroll
        for (int r = 0; r < 4; ++r) {
            const uint4 v = wr[r];
            h2 = __hfma2(enc2[4 * r + 0], *(const __nv_bfloat162*)&v.x, h2);
            h2 = __hfma2(enc2[4 * r + 1], *(const __nv_bfloat162*)&v.y, h2);
            h2 = __hfma2(enc2[4 * r + 2], *(const __nv_bfloat162*)&v.z, h2);
            h2 = __hfma2(enc2[4 * r + 3], *(const __nv_bfloat162*)&v.w, h2);
        }
        const float h = __low2float(h2) + __high2float(h2);
        acc = fmaf(s_w2[jbase + j], fmaxf(h, 0.0f), acc);
    }
    acc += __shfl_xor_sync(0xffffffffu, acc, 1);
    if (q == 0) out[p] = 1.0f / (1.0f + __expf(-acc));
}

extern "C" void kernel_launch(void* const* d_in, const int* in_sizes, int n_in,
                              void* d_out, int out_size)
{
    const float*  pts   = (const float*)d_in[0];   // [NPTS, 3]
    const float2* table = (const float2*)d_in[1];  // [L, T, 2]
    const float*  w1    = (const float*)d_in[2];   // [64, 32]
    const float*  w2    = (const float*)d_in[3];   // [64]
    float* out = (float*)d_out;

    prep_weights_kernel<<<1, 256>>>(w1);
    ngp_fused_bf16_kernel<<<(NPTS * 2) / 256, 256>>>(pts, table, w2, out);
}

// round 4
// speedup vs baseline: 1.6184x; 1.2131x over previous
#include <cuda_runtime.h>
#include <cuda_bf16.h>
#include <math.h>

// instant-NGP HashGrid + 2-layer MLP, fused. 2 lanes/point (x-corner pairing),
// bf16x2 MLP (HFMA2). R4: interleaved j-split (conflict-free LDS), explicit
// per-level load batching (guaranteed MLP>=4), L1 reserved for levels 0-2.

#define NPTS (64 * 64 * 64)
#define NLEV 16
#define TSIZE (1u << 19)
#define TMASK (TSIZE - 1u)

__device__ __nv_bfloat162 g_w1p[64 * 16];   // [j][l] packed pairs of w1[j, 2l:2l+2]

__global__ void prep_weights_kernel(const float* __restrict__ w1) {
    for (int k = threadIdx.x; k < 64 * 16; k += 256) {
        const int j = k >> 4, l = k & 15;
        g_w1p[k] = __floats2bfloat162_rn(w1[j * 32 + 2 * l], w1[j * 32 + 2 * l + 1]);
    }
}

__device__ __forceinline__ int level_res(int l) {
    const int R[NLEV] = {16, 23, 33, 48, 70, 101, 147, 212,
                         307, 445, 645, 933, 1351, 1955, 2830, 4096};
    return R[l];
}

__global__ void __launch_bounds__(256, 6)
ngp_fused_r4_kernel(const float* __restrict__ pts,
                    const float2* __restrict__ table,   // [L*T] float2
                    const float* __restrict__ w2,       // [64]
                    float* __restrict__ out)            // [NPTS]
{
    __shared__ __nv_bfloat162 s_w1p[64 * 16];
    __shared__ float s_w2[64];

    const int tid = threadIdx.x;
    for (int i = tid; i < 64 * 16; i += 256) s_w1p[i] = g_w1p[i];
    if (tid < 64) s_w2[tid] = w2[tid];
    __syncthreads();

    const int t = blockIdx.x * 256 + tid;
    const int p = t >> 1;        // point id
    const int q = t & 1;         // which x-corner this lane owns

    const float px = pts[3 * p + 0];
    const float py = pts[3 * p + 1];
    const float pz = pts[3 * p + 2];

    __nv_bfloat162 enc2[NLEV];   // packed (e0,e1) per level

#pragma unroll
    for (int l = 0; l < NLEV; ++l) {
        const int resi = level_res(l);
        const bool dense = (l < 5);
        const bool keepL1 = (l < 3);           // only these fit in L1
        const float res = (float)resi;

        const float x = px * res, y = py * res, z = pz * res;
        const float fx0 = floorf(x), fy0 = floorf(y), fz0 = floorf(z);
        const float fx = x - fx0, fy = y - fy0, fz = z - fz0;
        const unsigned cx = (unsigned)fx0;
        const unsigned cy = (unsigned)fy0;
        const unsigned cz = (unsigned)fz0;

        const float2* __restrict__ tab = table + (size_t)l * TSIZE;

        const unsigned ux = cx + (unsigned)q;        // this lane's x corner
        const float wxq = q ? fx : (1.0f - fx);
        const float wy[2] = {1.0f - fy, fy};
        const float wz[2] = {1.0f - fz, fz};

        unsigned iy[2], iz[2];
        if (dense) {
            const unsigned r1 = (unsigned)(resi + 1);
            iy[0] = r1 * cy;       iy[1] = r1 * (cy + 1u);
            iz[0] = r1 * r1 * cz;  iz[1] = r1 * r1 * (cz + 1u);
        } else {
            iy[0] = cy * 2654435761u;        iy[1] = (cy + 1u) * 2654435761u;
            iz[0] = cz * 805459861u;         iz[1] = (cz + 1u) * 805459861u;
        }

        // compute all 4 addresses, issue all 4 loads, THEN accumulate
        unsigned idx[4];
#pragma unroll
        for (int c = 0; c < 4; ++c) {
            const int oy = (c >> 1) & 1, oz = c & 1;
            idx[c] = dense ? ((ux + iy[oy] + iz[oz]) & TMASK)
                           : ((ux ^ iy[oy] ^ iz[oz]) & TMASK);
        }
        float2 f[4];
#pragma unroll
        for (int c = 0; c < 4; ++c)
            f[c] = keepL1 ? __ldg(tab + idx[c]) : __ldcg(tab + idx[c]);

        float e0 = 0.0f, e1 = 0.0f;
#pragma unroll
        for (int c = 0; c < 4; ++c) {
            const int oy = (c >> 1) & 1, oz = c & 1;
            const float w = wxq * wy[oy] * wz[oz];
            e0 = fmaf(w, f[c].x, e0);
            e1 = fmaf(w, f[c].y, e1);
        }
        // combine the two x-corner halves across the lane pair
        e0 += __shfl_xor_sync(0xffffffffu, e0, 1);
        e1 += __shfl_xor_sync(0xffffffffu, e1, 1);
        enc2[l] = __floats2bfloat162_rn(e0, e1);
    }

    // MLP in bf16x2: lane q handles rows {2*jj + q} -> lane-pair shared
    // addresses are 64B apart = disjoint bank halves = conflict-free LDS.
    float acc = 0.0f;
#pragma unroll 4
    for (int jj = 0; jj < 32; ++jj) {
        const int row = 2 * jj + q;
        const uint4* __restrict__ wr = (const uint4*)(s_w1p + row * 16);
        __nv_bfloat162 h2 = __floats2bfloat162_rn(0.0f, 0.0f);
#pragma unroll
        for (int r = 0; r < 4; ++r) {
            const uint4 v = wr[r];
            h2 = __hfma2(enc2[4 * r + 0], *(const __nv_bfloat162*)&v.x, h2);
            h2 = __hfma2(enc2[4 * r + 1], *(const __nv_bfloat162*)&v.y, h2);
            h2 = __hfma2(enc2[4 * r + 2], *(const __nv_bfloat162*)&v.z, h2);
            h2 = __hfma2(enc2[4 * r + 3], *(const __nv_bfloat162*)&v.w, h2);
        }
        const float h = __low2float(h2) + __high2float(h2);
        acc = fmaf(s_w2[row], fmaxf(h, 0.0f), acc);
    }
    acc += __shfl_xor_sync(0xffffffffu, acc, 1);
    if (q == 0) out[p] = 1.0f / (1.0f + __expf(-acc));
}

extern "C" void kernel_launch(void* const* d_in, const int* in_sizes, int n_in,
                              void* d_out, int out_size)
{
    const float*  pts   = (const float*)d_in[0];   // [NPTS, 3]
    const float2* table = (const float2*)d_in[1];  // [L, T, 2]
    const float*  w1    = (const float*)d_in[2];   // [64, 32]
    const float*  w2    = (const float*)d_in[3];   // [64]
    float* out = (float*)d_out;

    prep_weights_kernel<<<1, 256>>>(w1);
    ngp_fused_r4_kernel<<<(NPTS * 2) / 256, 256>>>(pts, table, w2, out);
}